// round 1
// baseline (speedup 1.0000x reference)
#include <cuda_runtime.h>
#include <cuda_bf16.h>

// QuantizedGRU: T=512, B=1024, H=12, Q7 fixed point (scale 128).
// Strategy:
//   - Work in the x128 "scaled" domain: every quantized value is an
//     integer-valued float. quantize == round-to-nearest-even == 2 FADDs
//     (magic constant). All arithmetic is exact in fp32 (proved by range
//     analysis), so results match the JAX reference bit-for-bit.
//   - Prepass kernel precomputes ii = quantize(x*W_ih)+b_ih for all (t,b)
//     into a __device__ scratch laid out for the serial kernel's threads.
//   - Serial kernel: 4 threads per batch element (thread owns gate indices
//     3s..3s+2 => rows i, i+12, i+24 of W_hh), h broadcast via shuffles.
//     128 blocks x 32 threads -> one warp per SM.

#define TT 512
#define BB 1024

// Scratch: [t][b][s][12] floats, slots 0..8 = (ii+b) for rows (3s+c+12g),
// slot index = 3*c + g; slots 9..11 pad. 100.7 MB.
__device__ __align__(16) float g_A[TT * BB * 48];

__device__ __forceinline__ float rne(float v) {
    // round-to-nearest-even for |v| < 2^22 (magic constant trick)
    return __fadd_rn(__fadd_rn(v, 12582912.0f), -12582912.0f);
}
__device__ __forceinline__ float rneq(float v) {
    // full quantize in scaled domain: round then clip to int16 range
    return fminf(fmaxf(rne(v), -32768.0f), 32767.0f);
}

// ---------------------------------------------------------------------------
// Prepass: one thread per scratch element (perfectly coalesced writes).
// ---------------------------------------------------------------------------
__global__ void prep_kernel(const float* __restrict__ x,
                            const float* __restrict__ wih,
                            const float* __restrict__ bih) {
    int idx = blockIdx.x * blockDim.x + threadIdx.x;   // < TT*BB*48
    int e  = idx % 12;
    int s  = (idx / 12) & 3;
    int tb = idx / 48;
    float val = 0.0f;
    if (e < 9) {
        int c = e / 3, g = e % 3;
        int row = 3 * s + c + 12 * g;
        // quantized scaled weight/bias
        float ws = rneq(__fmul_rn(wih[row], 128.0f));   // = Wq_real * 128
        float bs = rneq(__fmul_rn(bih[row], 128.0f));
        // ii_s = round(x * Wq_real * 128) ; x*ws == (x*Wq_real)*128 exactly
        val = rneq(__fmul_rn(x[tb], ws)) + bs;          // both integers: exact
    }
    g_A[idx] = val;
}

// ---------------------------------------------------------------------------
// Serial GRU kernel: 128 blocks x 32 threads; thread = (batch b, sub s).
// ---------------------------------------------------------------------------
__global__ void __launch_bounds__(32) gru_kernel(
        const float* __restrict__ whh_raw, const float* __restrict__ bhh_raw,
        const float* __restrict__ w1_raw,  const float* __restrict__ b1_raw,
        const float* __restrict__ w2_raw,  const float* __restrict__ b2_raw,
        float* __restrict__ out) {
    __shared__ float whh[432];   // quantized W_hh, real domain, [36][12]

    const int lane = threadIdx.x;
    for (int i = lane; i < 432; i += 32)
        whh[i] = __fmul_rn(rneq(__fmul_rn(whh_raw[i], 128.0f)), 0.0078125f);
    __syncthreads();

    const int s  = lane & 3;
    const int b  = (blockIdx.x << 3) + (lane >> 2);
    const int i0 = 3 * s;

    // scaled biases for owned rows: [c][g], g: 0=r,1=z,2=n
    float bhhs[3][3];
#pragma unroll
    for (int c = 0; c < 3; ++c)
#pragma unroll
        for (int g = 0; g < 3; ++g)
            bhhs[c][g] = rneq(__fmul_rn(bhh_raw[i0 + c + 12 * g], 128.0f));

    // fcnn split: threads 0..2 own W1 rows (2s, 2s+1); thread 3 duplicates
    // rows (0,1) with zero w2 so its partial vanishes.
    const int r0 = (s == 3) ? 0 : 2 * s;
    float W1r[2][12], b1s[2], w2r[2];
#pragma unroll
    for (int j = 0; j < 2; ++j) {
#pragma unroll
        for (int k = 0; k < 12; ++k)
            W1r[j][k] = __fmul_rn(rneq(__fmul_rn(w1_raw[(r0 + j) * 12 + k], 128.0f)),
                                  0.0078125f);
        b1s[j] = rneq(__fmul_rn(b1_raw[r0 + j], 128.0f));
        w2r[j] = (s == 3) ? 0.0f
                 : __fmul_rn(rneq(__fmul_rn(w2_raw[r0 + j], 128.0f)), 0.0078125f);
    }
    const float b2s = rneq(__fmul_rn(b2_raw[0], 128.0f));

    // state (scaled domain)
    float h[12];
#pragma unroll
    for (int k = 0; k < 12; ++k) h[k] = 0.0f;
    float hown0 = 0.0f, hown1 = 0.0f, hown2 = 0.0f;

    const float4* Ap = reinterpret_cast<const float4*>(g_A);
    const int tstride = BB * 12;               // float4 per timestep
    int base = b * 12 + s * 3;
    float4 A0 = Ap[base], A1 = Ap[base + 1], A2 = Ap[base + 2];
    const int grp = lane & ~3;

#pragma unroll 1
    for (int t = 0; t < TT; ++t) {
        // prefetch next step's ii tile
        const int nb = base + ((t < TT - 1) ? tstride : 0);
        const float4 N0 = Ap[nb], N1 = Ap[nb + 1], N2 = Ap[nb + 2];
        base = nb;

        const float a[12] = {A0.x, A0.y, A0.z, A0.w,
                             A1.x, A1.y, A1.z, A1.w,
                             A2.x, A2.y, A2.z, A2.w};
        float hn[3];
#pragma unroll
        for (int c = 0; c < 3; ++c) {
            const float* wr = &whh[(i0 + c) * 12];
            float ar = 0.0f, az = 0.0f, an = 0.0f;
#pragma unroll
            for (int k = 0; k < 12; ++k) {
                ar = __fmaf_rn(h[k], wr[k], ar);
                az = __fmaf_rn(h[k], wr[k + 144], az);
                an = __fmaf_rn(h[k], wr[k + 288], an);
            }
            const float hhr = rneq(ar) + bhhs[c][0];   // quantize + bias (exact)
            const float hhz = rneq(az) + bhhs[c][1];
            const float hhn = rneq(an) + bhhs[c][2];

            // hard sigmoid, scaled: clip(0.25*v + 64, 0, 128) then round
            const float rt = rne(fminf(fmaxf(
                __fmaf_rn(0.25f, a[3 * c + 0] + hhr, 64.0f), 0.0f), 128.0f));
            const float zt = rne(fminf(fmaxf(
                __fmaf_rn(0.25f, a[3 * c + 1] + hhz, 64.0f), 0.0f), 128.0f));

            // n gate: clip(ii + rt*hhn/128, -128, 128) then round
            const float np = __fmaf_rn(__fmul_rn(rt, hhn), 0.0078125f, a[3 * c + 2]);
            const float nt = rne(fminf(fmaxf(np, -128.0f), 128.0f));

            // h' = round(((128-zt)*nt + zt*h)/128)  (exact integer arithmetic)
            const float ho = (c == 0) ? hown0 : ((c == 1) ? hown1 : hown2);
            const float hv = __fmaf_rn(128.0f - zt, nt, __fmul_rn(zt, ho));
            hn[c] = rne(__fmul_rn(hv, 0.0078125f));
        }
        hown0 = hn[0]; hown1 = hn[1]; hown2 = hn[2];

        // broadcast full h: owner sub = i/3, slot = i%3
#pragma unroll
        for (int i = 0; i < 12; ++i)
            h[i] = __shfl_sync(0xffffffffu, hn[i % 3], grp + (i / 3));

        // fcnn on h_new
        float oa = 0.0f, ob = 0.0f;
#pragma unroll
        for (int k = 0; k < 12; ++k) {
            oa = __fmaf_rn(h[k], W1r[0][k], oa);
            ob = __fmaf_rn(h[k], W1r[1][k], ob);
        }
        const float q1a = rneq(oa) + b1s[0];
        const float q1b = rneq(ob) + b1s[1];
        float p = __fmaf_rn(fmaxf(q1a, 0.0f), w2r[0],
                            __fmul_rn(fmaxf(q1b, 0.0f), w2r[1]));
        p += __shfl_xor_sync(0xffffffffu, p, 1);
        p += __shfl_xor_sync(0xffffffffu, p, 2);
        const float o2 = rneq(p) + b2s;
        if (s == 0) out[t * BB + b] = __fmul_rn(o2, 0.0078125f);

        A0 = N0; A1 = N1; A2 = N2;
    }
}

// ---------------------------------------------------------------------------
extern "C" void kernel_launch(void* const* d_in, const int* in_sizes, int n_in,
                              void* d_out, int out_size) {
    const float* input = (const float*)d_in[0];
    const float* wih   = (const float*)d_in[1];
    const float* whh   = (const float*)d_in[2];
    const float* bih   = (const float*)d_in[3];
    const float* bhh   = (const float*)d_in[4];
    const float* w1    = (const float*)d_in[5];
    const float* b1    = (const float*)d_in[6];
    const float* w2    = (const float*)d_in[7];
    const float* b2    = (const float*)d_in[8];
    float* out = (float*)d_out;

    const int prep_elems = TT * BB * 48;
    prep_kernel<<<prep_elems / 256, 256>>>(input, wih, bih);
    gru_kernel<<<BB / 8, 32>>>(whh, bhh, w1, b1, w2, b2, out);
}

// round 2
// speedup vs baseline: 1.3596x; 1.3596x over previous
#include <cuda_runtime.h>
#include <cuda_bf16.h>

// QuantizedGRU: T=512, B=1024, H=12, Q7 fixed point (scale 128).
// Round 2: 16 threads per batch element.
//   lane r (0..11): owns gate triple i=r (W_hh rows r, r+12, r+24)
//   lane 12,13    : own FCNN rows (W1 rows 0-2 / 3-5), pipelined 1 step behind
//   lane 14,15    : zero weights (same instruction stream, results unused)
// All lanes execute ONE identical 3-row packed dot per step (fma.rn.f32x2),
// weights live in registers. 128 blocks x 128 threads -> 1 warp per SMSP on
// 128 SMs (vs 1 warp per SM before). Entire computation stays in the exact
// x128 scaled-integer fp32 domain (bit-exact vs reference, proven round 1).

#define TT 512
#define BB 1024
#define INV 0.0078125f

// Scratch: [t][b][12]x float4  (ii_r, ii_z, ii_n, pad) per gate-triple. 100.7MB
__device__ __align__(16) float g_A[TT * BB * 12 * 4];

__device__ __forceinline__ float rne(float v) {
    // round-to-nearest-even for |v| < 2^22 (magic constant trick)
    return __fadd_rn(__fadd_rn(v, 12582912.0f), -12582912.0f);
}
__device__ __forceinline__ float rneq(float v) {
    return fminf(fmaxf(rne(v), -32768.0f), 32767.0f);
}
__device__ __forceinline__ float qr(float v) {
    // quantize a raw weight, return real-domain value (multiple of 1/128)
    return __fmul_rn(rneq(__fmul_rn(v, 128.0f)), INV);
}
__device__ __forceinline__ unsigned long long pk2(float lo, float hi) {
    unsigned long long r;
    asm("mov.b64 %0, {%1, %2};" : "=l"(r) : "f"(lo), "f"(hi));
    return r;
}
__device__ __forceinline__ void fma2(unsigned long long& d,
                                     unsigned long long a,
                                     unsigned long long b) {
    asm("fma.rn.f32x2 %0, %1, %2, %0;" : "+l"(d) : "l"(a), "l"(b));
}
__device__ __forceinline__ float hsum2(unsigned long long v) {
    float lo, hi;
    asm("mov.b64 {%0, %1}, %2;" : "=f"(lo), "=f"(hi) : "l"(v));
    return __fadd_rn(lo, hi);
}

// ---------------------------------------------------------------------------
// Prepass: one thread per float4 (perfectly coalesced 16B writes).
// ---------------------------------------------------------------------------
__global__ void prep_kernel(const float* __restrict__ x,
                            const float* __restrict__ wih,
                            const float* __restrict__ bih) {
    int idx = blockIdx.x * blockDim.x + threadIdx.x;  // < TT*BB*12
    int r  = idx % 12;
    int tb = idx / 12;
    float xv = __ldg(&x[tb]);
    float4 v;
    float w0 = rneq(__fmul_rn(__ldg(&wih[r]),      128.0f));
    float w1 = rneq(__fmul_rn(__ldg(&wih[r + 12]), 128.0f));
    float w2 = rneq(__fmul_rn(__ldg(&wih[r + 24]), 128.0f));
    float b0 = rneq(__fmul_rn(__ldg(&bih[r]),      128.0f));
    float b1 = rneq(__fmul_rn(__ldg(&bih[r + 12]), 128.0f));
    float b2 = rneq(__fmul_rn(__ldg(&bih[r + 24]), 128.0f));
    v.x = rneq(__fmul_rn(xv, w0)) + b0;   // both integers: exact add
    v.y = rneq(__fmul_rn(xv, w1)) + b1;
    v.z = rneq(__fmul_rn(xv, w2)) + b2;
    v.w = 0.0f;
    reinterpret_cast<float4*>(g_A)[idx] = v;
}

// ---------------------------------------------------------------------------
// Serial GRU kernel: 128 blocks x 128 threads (8 batches/block, 16 thr/batch)
// ---------------------------------------------------------------------------
__global__ void __launch_bounds__(128, 1) gru_kernel(
        const float* __restrict__ whh_raw, const float* __restrict__ bhh_raw,
        const float* __restrict__ w1_raw,  const float* __restrict__ b1_raw,
        const float* __restrict__ w2_raw,  const float* __restrict__ b2_raw,
        float* __restrict__ out) {
    const int r = threadIdx.x & 15;                      // role within batch
    const int b = (blockIdx.x << 3) + (threadIdx.x >> 4);

    // --- per-lane packed weight rows (real domain) + scaled biases ---
    unsigned long long wA[6], wB[6], wC[6];
    float biasA = 0.f, biasB = 0.f, biasC = 0.f;
    float w2a = 0.f, w2b = 0.f, w2c = 0.f;
#pragma unroll
    for (int k = 0; k < 6; ++k) { wA[k] = 0; wB[k] = 0; wC[k] = 0; }

    if (r < 12) {
        const float* pA = whh_raw + r * 12;
        const float* pB = whh_raw + (r + 12) * 12;
        const float* pC = whh_raw + (r + 24) * 12;
#pragma unroll
        for (int k = 0; k < 6; ++k) {
            wA[k] = pk2(qr(pA[2 * k]), qr(pA[2 * k + 1]));
            wB[k] = pk2(qr(pB[2 * k]), qr(pB[2 * k + 1]));
            wC[k] = pk2(qr(pC[2 * k]), qr(pC[2 * k + 1]));
        }
        biasA = rneq(__fmul_rn(bhh_raw[r],      128.0f));
        biasB = rneq(__fmul_rn(bhh_raw[r + 12], 128.0f));
        biasC = rneq(__fmul_rn(bhh_raw[r + 24], 128.0f));
    } else if (r < 14) {
        const int r0 = (r - 12) * 3;
        const float* pA = w1_raw + (r0 + 0) * 12;
        const float* pB = w1_raw + (r0 + 1) * 12;
        const float* pC = w1_raw + (r0 + 2) * 12;
#pragma unroll
        for (int k = 0; k < 6; ++k) {
            wA[k] = pk2(qr(pA[2 * k]), qr(pA[2 * k + 1]));
            wB[k] = pk2(qr(pB[2 * k]), qr(pB[2 * k + 1]));
            wC[k] = pk2(qr(pC[2 * k]), qr(pC[2 * k + 1]));
        }
        biasA = rneq(__fmul_rn(b1_raw[r0 + 0], 128.0f));
        biasB = rneq(__fmul_rn(b1_raw[r0 + 1], 128.0f));
        biasC = rneq(__fmul_rn(b1_raw[r0 + 2], 128.0f));
        w2a = qr(w2_raw[r0 + 0]);
        w2b = qr(w2_raw[r0 + 1]);
        w2c = qr(w2_raw[r0 + 2]);
    }
    const float b2s = rneq(__fmul_rn(b2_raw[0], 128.0f));

    // --- state: h packed (scaled domain), own component ---
    unsigned long long hp[6];
#pragma unroll
    for (int k = 0; k < 6; ++k) hp[k] = 0;
    float h_own = 0.0f;

    const float4* Ap = reinterpret_cast<const float4*>(g_A);
    const int rr = (r < 12) ? r : (r - 12);       // lanes 12-15 read dummy
    const int tstr = BB * 12;
    int base = b * 12 + rr;
    float4 cur = Ap[base];

#pragma unroll 1
    for (int t = 0; t <= TT; ++t) {
        // prefetch next step's ii triple
        const int nb = base + ((t < TT - 1) ? tstr : 0);
        const float4 nxt = Ap[nb];
        base = nb;

        // --- unified 3-row packed dot with current h (= h_{t-1}) ---
        unsigned long long aA = 0, aB = 0, aC = 0;
#pragma unroll
        for (int k = 0; k < 6; ++k) {
            fma2(aA, hp[k], wA[k]);
            fma2(aB, hp[k], wB[k]);
            fma2(aC, hp[k], wC[k]);
        }
        const float qA = rneq(hsum2(aA)) + biasA;   // gate lanes: hh_r/z/n
        const float qB = rneq(hsum2(aB)) + biasB;   // fcnn lanes: q1 rows
        const float qC = rneq(hsum2(aC)) + biasC;

        // --- fcnn epilogue (lanes 12,13), output for step t-1 ---
        float pa = __fmaf_rn(fmaxf(qA, 0.0f), w2a,
                   __fmaf_rn(fmaxf(qB, 0.0f), w2b,
                   __fmul_rn(fmaxf(qC, 0.0f), w2c)));
        const float p = pa + __shfl_xor_sync(0xffffffffu, pa, 1);
        if (r == 12 && t > 0)
            out[(t - 1) * BB + b] = __fmul_rn(rneq(p) + b2s, INV);

        // --- gate epilogue (lanes 0-11): compute h_t component ---
        const float rt = rne(fminf(fmaxf(
            __fmaf_rn(0.25f, cur.x + qA, 64.0f), 0.0f), 128.0f));
        const float zt = rne(fminf(fmaxf(
            __fmaf_rn(0.25f, cur.y + qB, 64.0f), 0.0f), 128.0f));
        const float nt = rne(fminf(fmaxf(
            __fmaf_rn(__fmul_rn(rt, qC), INV, cur.z), -128.0f), 128.0f));
        const float hv = __fmaf_rn(128.0f - zt, nt, __fmul_rn(zt, h_own));
        const float hn = rne(__fmul_rn(hv, INV));
        h_own = hn;

        // --- broadcast h_t across the 16-lane group, repack ---
#pragma unroll
        for (int k = 0; k < 6; ++k) {
            const float lo = __shfl_sync(0xffffffffu, hn, 2 * k,     16);
            const float hi = __shfl_sync(0xffffffffu, hn, 2 * k + 1, 16);
            hp[k] = pk2(lo, hi);
        }
        cur = nxt;
    }
}

// ---------------------------------------------------------------------------
extern "C" void kernel_launch(void* const* d_in, const int* in_sizes, int n_in,
                              void* d_out, int out_size) {
    const float* input = (const float*)d_in[0];
    const float* wih   = (const float*)d_in[1];
    const float* whh   = (const float*)d_in[2];
    const float* bih   = (const float*)d_in[3];
    const float* bhh   = (const float*)d_in[4];
    const float* w1    = (const float*)d_in[5];
    const float* b1    = (const float*)d_in[6];
    const float* w2    = (const float*)d_in[7];
    const float* b2    = (const float*)d_in[8];
    float* out = (float*)d_out;

    const int prep_elems = TT * BB * 12;           // float4 count
    prep_kernel<<<prep_elems / 256, 256>>>(input, wih, bih);
    gru_kernel<<<BB / 8, 128>>>(whh, bhh, w1, b1, w2, b2, out);
}

// round 3
// speedup vs baseline: 6.4671x; 4.7567x over previous
#include <cuda_runtime.h>
#include <cuda_bf16.h>

// QuantizedGRU: T=512, B=1024, H=12, Q7 fixed point (scale 128).
// Round 3: no prepass, no DRAM in the loop.
//   - Block owns 8 batches; stages all 512 x-values per batch into smem
//     (16KB) in a prologue. Per step: one broadcast LDS (prefetched).
//   - 16 threads per batch: lanes 0-11 own gate triple i (W_hh rows i,i+12,
//     i+24); lanes 12,13 own FCNN rows (pipelined 1 step behind); 14,15 pad.
//   - Dot products use packed fma.rn.f32x2, split into 2x3-deep chains.
//   - Entire computation in the exact x128 scaled-integer fp32 domain
//     (bit-exact, proven rounds 1-2). Clips that cannot fire are dropped
//     (|values| << 32768, so quantize's clip is a no-op there).

#define TT 512
#define BB 1024
#define INV 0.0078125f

typedef unsigned long long u64;

__device__ __forceinline__ float rne(float v) {
    // round-to-nearest-even for |v| < 2^22
    return __fadd_rn(__fadd_rn(v, 12582912.0f), -12582912.0f);
}
__device__ __forceinline__ float rneq(float v) {
    return fminf(fmaxf(rne(v), -32768.0f), 32767.0f);
}
__device__ __forceinline__ float qs(float v) {   // quantized weight, scaled
    return rneq(__fmul_rn(v, 128.0f));
}
__device__ __forceinline__ float qr(float v) {   // quantized weight, real
    return __fmul_rn(qs(v), INV);
}
__device__ __forceinline__ u64 pk2(float lo, float hi) {
    u64 r;
    asm("mov.b64 %0, {%1, %2};" : "=l"(r) : "f"(lo), "f"(hi));
    return r;
}
__device__ __forceinline__ void fma2(u64& d, u64 a, u64 b) {
    asm("fma.rn.f32x2 %0, %1, %2, %0;" : "+l"(d) : "l"(a), "l"(b));
}
__device__ __forceinline__ u64 add2(u64 a, u64 b) {
    u64 r;
    asm("add.rn.f32x2 %0, %1, %2;" : "=l"(r) : "l"(a), "l"(b));
    return r;
}
__device__ __forceinline__ float hsum2(u64 v) {
    float lo, hi;
    asm("mov.b64 {%0, %1}, %2;" : "=f"(lo), "=f"(hi) : "l"(v));
    return __fadd_rn(lo, hi);
}

// ---------------------------------------------------------------------------
// Single kernel: 128 blocks x 128 threads (8 batches/block, 16 thr/batch)
// ---------------------------------------------------------------------------
__global__ void __launch_bounds__(128, 1) gru_kernel(
        const float* __restrict__ x,
        const float* __restrict__ wih_raw, const float* __restrict__ whh_raw,
        const float* __restrict__ bih_raw, const float* __restrict__ bhh_raw,
        const float* __restrict__ w1_raw,  const float* __restrict__ b1_raw,
        const float* __restrict__ w2_raw,  const float* __restrict__ b2_raw,
        float* __restrict__ out) {
    __shared__ float xs[TT * 8];          // [t][bb] x-values for this block

    const int tid = threadIdx.x;
    const int r   = tid & 15;             // role within batch
    const int bb  = tid >> 4;             // batch within block
    const int b0  = blockIdx.x << 3;
    const int b   = b0 + bb;

    // --- stage x into smem (coalesced 32B rows) ---
    for (int i = tid; i < TT * 8; i += 128) {
        const int t  = i >> 3;
        const int bj = i & 7;
        xs[i] = x[t * BB + b0 + bj];
    }

    // --- per-lane weights (packed, real domain) & scaled bias folds ---
    u64 wA[6], wB[6], wC[6];
    float ws0 = 0.f, ws1 = 0.f, ws2 = 0.f;        // scaled W_ih entries
    float cb0 = 0.f, cb1 = 0.f, cb2 = 0.f, cC = 0.f;
    float w2a = 0.f, w2b = 0.f, w2c = 0.f;
#pragma unroll
    for (int k = 0; k < 6; ++k) { wA[k] = 0; wB[k] = 0; wC[k] = 0; }

    if (r < 12) {
        const float* pA = whh_raw + r * 12;
        const float* pB = whh_raw + (r + 12) * 12;
        const float* pC = whh_raw + (r + 24) * 12;
#pragma unroll
        for (int k = 0; k < 6; ++k) {
            wA[k] = pk2(qr(pA[2 * k]), qr(pA[2 * k + 1]));
            wB[k] = pk2(qr(pB[2 * k]), qr(pB[2 * k + 1]));
            wC[k] = pk2(qr(pC[2 * k]), qr(pC[2 * k + 1]));
        }
        ws0 = qs(wih_raw[r]);
        ws1 = qs(wih_raw[r + 12]);
        ws2 = qs(wih_raw[r + 24]);
        cb0 = qs(bih_raw[r])      + qs(bhh_raw[r]);       // exact int add
        cb1 = qs(bih_raw[r + 12]) + qs(bhh_raw[r + 12]);
        cb2 = qs(bih_raw[r + 24]);
        cC  = qs(bhh_raw[r + 24]);
    } else if (r < 14) {
        const int r0 = (r - 12) * 3;
#pragma unroll
        for (int j = 0; j < 3; ++j) {
            const float* p = w1_raw + (r0 + j) * 12;
            u64* w = (j == 0) ? wA : ((j == 1) ? wB : wC);
#pragma unroll
            for (int k = 0; k < 6; ++k)
                w[k] = pk2(qr(p[2 * k]), qr(p[2 * k + 1]));
        }
        cb0 = qs(b1_raw[r0 + 0]);
        cb1 = qs(b1_raw[r0 + 1]);
        cC  = qs(b1_raw[r0 + 2]);
        w2a = qr(w2_raw[r0 + 0]);
        w2b = qr(w2_raw[r0 + 1]);
        w2c = qr(w2_raw[r0 + 2]);
    }
    const float b2s = qs(b2_raw[0]);

    __syncthreads();

    // --- state (scaled domain) ---
    u64 hp[6];
#pragma unroll
    for (int k = 0; k < 6; ++k) hp[k] = 0;
    float h_own = 0.0f;

    float xcur = xs[bb];                  // x for t = 0

#pragma unroll 1
    for (int t = 0; t <= TT; ++t) {
        // x prefetch for next step (off critical path, broadcast LDS)
        const int tn = (t < TT - 1) ? (t + 1) : (TT - 1);
        const float xnext = xs[tn * 8 + bb];

        // ii precompute (off critical path; exact integer adds)
        const float px0 = rne(__fmul_rn(xcur, ws0)) + cb0;  // ii_r + b_ih + b_hh
        const float px1 = rne(__fmul_rn(xcur, ws1)) + cb1;  // ii_z + b_ih + b_hh
        const float px2 = rne(__fmul_rn(xcur, ws2)) + cb2;  // ii_n + b_ih

        // --- 3-row packed dot with h_{t-1}: two 3-deep chains each ---
        u64 a0 = 0, a1 = 0, e0 = 0, e1 = 0, c0 = 0, c1 = 0;
        fma2(a0, hp[0], wA[0]); fma2(a0, hp[1], wA[1]); fma2(a0, hp[2], wA[2]);
        fma2(a1, hp[3], wA[3]); fma2(a1, hp[4], wA[4]); fma2(a1, hp[5], wA[5]);
        fma2(e0, hp[0], wB[0]); fma2(e0, hp[1], wB[1]); fma2(e0, hp[2], wB[2]);
        fma2(e1, hp[3], wB[3]); fma2(e1, hp[4], wB[4]); fma2(e1, hp[5], wB[5]);
        fma2(c0, hp[0], wC[0]); fma2(c0, hp[1], wC[1]); fma2(c0, hp[2], wC[2]);
        fma2(c1, hp[3], wC[3]); fma2(c1, hp[4], wC[4]); fma2(c1, hp[5], wC[5]);
        const float dA = hsum2(add2(a0, a1));
        const float dB = hsum2(add2(e0, e1));
        const float dC = hsum2(add2(c0, c1));

        // gate lanes: vA = ii_r + hh_r (+both biases); fcnn lanes: q1 rows
        const float vA = rne(dA) + px0;
        const float vB = rne(dB) + px1;
        const float qC = rne(dC) + cC;

        // --- fcnn epilogue (lanes 12,13): output for step t-1 ---
        float pa = __fmaf_rn(fmaxf(vA, 0.0f), w2a,
                   __fmaf_rn(fmaxf(vB, 0.0f), w2b,
                   __fmul_rn(fmaxf(qC, 0.0f), w2c)));
        const float p = pa + __shfl_xor_sync(0xffffffffu, pa, 1);
        if (r == 12 && t > 0)
            out[(t - 1) * BB + b] = __fmul_rn(rne(p) + b2s, INV);

        // --- gate epilogue (lanes 0-11): h_t component ---
        const float rt = rne(fminf(fmaxf(
            __fmaf_rn(0.25f, vA, 64.0f), 0.0f), 128.0f));
        const float zt = rne(fminf(fmaxf(
            __fmaf_rn(0.25f, vB, 64.0f), 0.0f), 128.0f));
        const float nt = rne(fminf(fmaxf(
            __fmaf_rn(__fmul_rn(rt, qC), INV, px2), -128.0f), 128.0f));
        const float hv = __fmaf_rn(128.0f - zt, nt, __fmul_rn(zt, h_own));
        const float hn = rne(__fmul_rn(hv, INV));
        h_own = hn;

        // --- broadcast h_t across the 16-lane group, repack ---
#pragma unroll
        for (int k = 0; k < 6; ++k) {
            const float lo = __shfl_sync(0xffffffffu, hn, 2 * k,     16);
            const float hi = __shfl_sync(0xffffffffu, hn, 2 * k + 1, 16);
            hp[k] = pk2(lo, hi);
        }
        xcur = xnext;
    }
}

// ---------------------------------------------------------------------------
extern "C" void kernel_launch(void* const* d_in, const int* in_sizes, int n_in,
                              void* d_out, int out_size) {
    const float* input = (const float*)d_in[0];
    const float* wih   = (const float*)d_in[1];
    const float* whh   = (const float*)d_in[2];
    const float* bih   = (const float*)d_in[3];
    const float* bhh   = (const float*)d_in[4];
    const float* w1    = (const float*)d_in[5];
    const float* b1    = (const float*)d_in[6];
    const float* w2    = (const float*)d_in[7];
    const float* b2    = (const float*)d_in[8];
    float* out = (float*)d_out;

    gru_kernel<<<BB / 8, 128>>>(input, wih, whh, bih, bhh,
                                w1, b1, w2, b2, out);
}